// round 8
// baseline (speedup 1.0000x reference)
#include <cuda_runtime.h>
#include <math.h>

#define NPTS   16384
#define BATCH  2
#define HBEV   200
#define WBEV   176
#define CBEV   256
#define HW     (HBEV*WBEV)
#define KTOT   2048
#define NROWS  (BATCH*KTOT)
#define CMPN   8192
#define FULLM  0xffffffffu
#define SCANBLK 128

// ---------------- static device scratch ----------------
__device__ float4 g_pts[BATCH*NPTS];       // SoA points: x,y,z,intensity
__device__ float  g_kp[NROWS*3];           // keypoint coords
__device__ int    g_ballidx[NROWS*32];     // [row][2][16] neighbor indices
__device__ int    g_ballcnt[NROWS*2];      // [row][2] capped counts

// ---------------- packed f32x2 + redux helpers ----------------
__device__ __forceinline__ unsigned long long pk2(float lo, float hi) {
    unsigned long long r; asm("mov.b64 %0, {%1, %2};" : "=l"(r) : "f"(lo), "f"(hi)); return r;
}
__device__ __forceinline__ void upk2(unsigned long long v, float& lo, float& hi) {
    asm("mov.b64 {%0, %1}, %2;" : "=f"(lo), "=f"(hi) : "l"(v));
}
__device__ __forceinline__ unsigned long long addx2(unsigned long long a, unsigned long long b) {
    unsigned long long r; asm("add.rn.f32x2 %0, %1, %2;" : "=l"(r) : "l"(a), "l"(b)); return r;
}
__device__ __forceinline__ unsigned long long mulx2(unsigned long long a, unsigned long long b) {
    unsigned long long r; asm("mul.rn.f32x2 %0, %1, %2;" : "=l"(r) : "l"(a), "l"(b)); return r;
}
__device__ __forceinline__ unsigned redux_maxu(unsigned v) {
    unsigned r; asm("redux.sync.max.u32 %0, %1, 0xffffffff;" : "=r"(r) : "r"(v)); return r;
}
__device__ __forceinline__ unsigned redux_minu(unsigned v) {
    unsigned r; asm("redux.sync.min.u32 %0, %1, 0xffffffff;" : "=r"(r) : "r"(v)); return r;
}
// argmax update: higher value wins, tie -> lower index (exact reference semantics)
__device__ __forceinline__ void upd(unsigned v, unsigned i, unsigned& bv, unsigned& bi) {
    if (v > bv || (v == bv && i < bi)) { bv = v; bi = i; }
}
__device__ __forceinline__ unsigned spread5(unsigned v) {
    v = (v | (v << 4)) & 0x0F0Fu;
    v = (v | (v << 2)) & 0x3333u;
    v = (v | (v << 1)) & 0x5555u;
    return v;
}

// ==================================================================
// FPS with exact chunk pruning (blocks 0..5) + SoA prep (blocks 6..63)
// Morton counting-sort -> 256-pt chunks with bbox + cached (maxD, idx).
// Skipped chunks contribute their cache; dirty chunks recompute exactly.
// ==================================================================
__global__ void __launch_bounds__(256,1) fps_kernel(const float* __restrict__ pts,
                                                    const float* __restrict__ rng,
                                                    float* __restrict__ coords_out) {
    extern __shared__ char dsm[];
    float4*         scmp = (float4*)dsm;                    // [8192] sorted pts (.w = origidx bits)
    float*          sD   = (float*)(dsm + 131072);          // [8192] current min-dist
    float2*         sD2  = (float2*)sD;
    unsigned short* inv  = (unsigned short*)(dsm + 163840); // origidx -> sorted pos
    __shared__ int      sCnt[1024];
    __shared__ float    sBB[32][8];
    __shared__ unsigned sCV[32];
    __shared__ unsigned sCI[32];
    __shared__ unsigned sv[2][8], si[2][8];
    __shared__ int wsum[8];
    __shared__ int s_tot;

    int t = threadIdx.x;
    if (blockIdx.x >= 6) {
        for (int i = ((int)blockIdx.x - 6)*256 + t; i < BATCH*NPTS; i += 58*256) {
            const float* p = pts + (size_t)i*5;
            g_pts[i] = make_float4(p[1], p[2], p[3], p[4]);
        }
        return;
    }

    int run = blockIdx.x, b = run/3, band = run - b*3;
    int lane = t & 31, w = t >> 5;

    for (int i = t; i < 1024; i += 256) sCnt[i] = 0;

    // ---- validity bits: 64 contiguous points per thread ----
    const float4* R4 = (const float4*)(rng + (size_t)b*NPTS) + t*16;
    unsigned long long bits = 0; int cnt = 0;
    #pragma unroll
    for (int q = 0; q < 16; q++) {
        float4 r4 = R4[q];
        float rr[4] = {r4.x, r4.y, r4.z, r4.w};
        #pragma unroll
        for (int u = 0; u < 4; u++) {
            float r = rr[u];
            bool sh = (r > 0.0f) && (r < 25.0f);
            bool lg = (r > 45.0f);
            bool v = (band == 0) ? sh : ((band == 2) ? lg : (!lg && !sh));
            if (v) { bits |= (1ull << (q*4+u)); cnt++; }
        }
    }
    // ---- original-order rank scan ----
    int inc = cnt;
    #pragma unroll
    for (int off = 1; off < 32; off <<= 1) {
        int o = __shfl_up_sync(FULLM, inc, off);
        if (lane >= off) inc += o;
    }
    if (lane == 31) wsum[w] = inc;
    __syncthreads();
    if (w == 0 && lane < 8) {
        int v = wsum[lane];
        #pragma unroll
        for (int off = 1; off < 8; off <<= 1) {
            int o = __shfl_up_sync(0xffu, v, off);
            if (lane >= off) v += o;
        }
        wsum[lane] = v;
        if (lane == 7) s_tot = v;
    }
    __syncthreads();
    int off0 = inc - cnt + (w ? wsum[w-1] : 0);

    // ---- pass 1: count Morton cells ----
    const float* PP = pts + (size_t)b*NPTS*5;
    {
        unsigned long long bb = bits;
        while (bb) {
            int u = __ffsll(bb) - 1; bb &= bb - 1;
            const float* p = PP + (size_t)(t*64 + u)*5;
            float x = p[1], y = p[2];
            int cx = min(31, max(0, (int)(x * 0.45454547f)));
            int cy = min(31, max(0, (int)((y + 40.0f) * 0.4f)));
            atomicAdd(&sCnt[spread5(cx) | (spread5(cy) << 1)], 1);
        }
    }
    __syncthreads();
    // ---- scan 1024 cell counts (4 per thread) ----
    {
        int c0 = sCnt[4*t], c1 = sCnt[4*t+1], c2 = sCnt[4*t+2], c3 = sCnt[4*t+3];
        int tot = c0 + c1 + c2 + c3;
        int inc2 = tot;
        #pragma unroll
        for (int off = 1; off < 32; off <<= 1) {
            int o = __shfl_up_sync(FULLM, inc2, off);
            if (lane >= off) inc2 += o;
        }
        if (lane == 31) wsum[w] = inc2;
        __syncthreads();
        if (w == 0 && lane < 8) {
            int v = wsum[lane];
            #pragma unroll
            for (int off = 1; off < 8; off <<= 1) {
                int o = __shfl_up_sync(0xffu, v, off);
                if (lane >= off) v += o;
            }
            wsum[lane] = v;
        }
        __syncthreads();
        int excl = inc2 - tot + (w ? wsum[w-1] : 0);
        sCnt[4*t]   = excl;
        sCnt[4*t+1] = excl + c0;
        sCnt[4*t+2] = excl + c0 + c1;
        sCnt[4*t+3] = excl + c0 + c1 + c2;
    }
    __syncthreads();
    // ---- pass 2: scatter into sorted order ----
    {
        int oi = off0;
        unsigned long long bb = bits;
        while (bb) {
            int u = __ffsll(bb) - 1; bb &= bb - 1;
            const float* p = PP + (size_t)(t*64 + u)*5;
            float x = p[1], y = p[2], z = p[3];
            int cx = min(31, max(0, (int)(x * 0.45454547f)));
            int cy = min(31, max(0, (int)((y + 40.0f) * 0.4f)));
            int cell = spread5(cx) | (spread5(cy) << 1);
            int pos = atomicAdd(&sCnt[cell], 1);
            if (oi < CMPN && pos < CMPN) {
                scmp[pos] = make_float4(x, y, z, __uint_as_float((unsigned)oi));
                inv[oi] = (unsigned short)pos;
                sD[pos] = 1e10f;
            }
            oi++;
        }
    }
    int M = min(s_tot, CMPN);
    for (int i = M + t; i < CMPN; i += 256) {
        scmp[i] = make_float4(1e8f, 1e8f, 1e8f, __uint_as_float(0xffffffffu));
        sD[i] = -1.0f;
    }
    __syncthreads();

    // ---- bbox + cache init per 256-pt chunk (warp w owns chunks w, w+8, ...) ----
    int SCtot = (M + 255) >> 8;
    for (int sc = w; sc < SCtot; sc += 8) {
        float xmn = 3e8f, xmx = -3e8f, ymn = 3e8f, ymx = -3e8f, zmn = 3e8f, zmx = -3e8f;
        unsigned omn = 0xffffffffu;
        #pragma unroll
        for (int q = 0; q < 4; q++) {
            int ip = sc*256 + q*64 + 2*lane;
            float4 pa = scmp[ip], pb = scmp[ip+1];
            unsigned oa = __float_as_uint(pa.w), ob = __float_as_uint(pb.w);
            if (oa != 0xffffffffu) {
                xmn = fminf(xmn, pa.x); xmx = fmaxf(xmx, pa.x);
                ymn = fminf(ymn, pa.y); ymx = fmaxf(ymx, pa.y);
                zmn = fminf(zmn, pa.z); zmx = fmaxf(zmx, pa.z);
                omn = min(omn, oa);
            }
            if (ob != 0xffffffffu) {
                xmn = fminf(xmn, pb.x); xmx = fmaxf(xmx, pb.x);
                ymn = fminf(ymn, pb.y); ymx = fmaxf(ymx, pb.y);
                zmn = fminf(zmn, pb.z); zmx = fmaxf(zmx, pb.z);
                omn = min(omn, ob);
            }
        }
        #pragma unroll
        for (int off = 16; off; off >>= 1) {
            xmn = fminf(xmn, __shfl_xor_sync(FULLM, xmn, off));
            xmx = fmaxf(xmx, __shfl_xor_sync(FULLM, xmx, off));
            ymn = fminf(ymn, __shfl_xor_sync(FULLM, ymn, off));
            ymx = fmaxf(ymx, __shfl_xor_sync(FULLM, ymx, off));
            zmn = fminf(zmn, __shfl_xor_sync(FULLM, zmn, off));
            zmx = fmaxf(zmx, __shfl_xor_sync(FULLM, zmx, off));
        }
        omn = redux_minu(omn);
        if (lane == 0) {
            sBB[sc][0] = xmn; sBB[sc][1] = xmx;
            sBB[sc][2] = ymn; sBB[sc][3] = ymx;
            sBB[sc][4] = zmn; sBB[sc][5] = zmx;
            sCV[sc] = (omn != 0xffffffffu) ? __float_as_uint(1e10f) : 0u;
            sCI[sc] = omn;
        }
    }
    __syncthreads();

    // ---- main sampling loop ----
    int K = (band == 0) ? 1024 : 512;
    int kpbase = b*KTOT + (band==0 ? 0 : (band==1 ? 1024 : 1536));
    int sel = inv[0];            // first valid original point
    for (int k = 0; ; k++) {
        float4 wp = scmp[sel];
        if (t == 0) {
            int r = kpbase + k;
            g_kp[r*3+0] = wp.x; g_kp[r*3+1] = wp.y; g_kp[r*3+2] = wp.z;
            coords_out[r*4+0] = (float)b;
            coords_out[r*4+1] = wp.x; coords_out[r*4+2] = wp.y; coords_out[r*4+3] = wp.z;
        }
        if (k == K-1) break;

        float wx = wp.x, wy = wp.y, wz = wp.z;
        unsigned long long nwx = pk2(-wx, -wx), nwy = pk2(-wy, -wy), nwz = pk2(-wz, -wz);
        unsigned bestb = 0u, besti = 0xffffffffu;

        for (int sc = w; sc < SCtot; sc += 8) {
            float dxb = fmaxf(fmaxf(sBB[sc][0] - wx, wx - sBB[sc][1]), 0.0f);
            float dyb = fmaxf(fmaxf(sBB[sc][2] - wy, wy - sBB[sc][3]), 0.0f);
            float dzb = fmaxf(fmaxf(sBB[sc][4] - wz, wz - sBB[sc][5]), 0.0f);
            float lb = dxb*dxb + dyb*dyb + dzb*dzb;
            unsigned cv = sCV[sc], ci = sCI[sc];
            if (lb * 0.999999f >= __uint_as_float(cv)) {
                upd(cv, ci, bestb, besti);          // exact cached chunk max
            } else {
                unsigned cmb = 0u, cmi = 0xffffffffu;
                int ip0 = sc*256 + 2*lane;
                #pragma unroll
                for (int q = 0; q < 4; q++) {
                    int ip = ip0 + q*64;
                    float4 pa = scmp[ip], pb = scmp[ip+1];
                    float2 Dp = sD2[ip >> 1];
                    unsigned long long px = pk2(pa.x, pb.x);
                    unsigned long long py = pk2(pa.y, pb.y);
                    unsigned long long pz = pk2(pa.z, pb.z);
                    unsigned long long dx = addx2(px, nwx);
                    unsigned long long dy = addx2(py, nwy);
                    unsigned long long dz = addx2(pz, nwz);
                    unsigned long long d2 = addx2(addx2(mulx2(dx,dx), mulx2(dy,dy)), mulx2(dz,dz));
                    float dl, dh; upk2(d2, dl, dh);
                    float n0 = fminf(Dp.x, dl), n1 = fminf(Dp.y, dh);
                    sD2[ip >> 1] = make_float2(n0, n1);
                    unsigned b0 = __float_as_uint(fmaxf(n0, 0.0f));
                    unsigned b1 = __float_as_uint(fmaxf(n1, 0.0f));
                    upd(b0, __float_as_uint(pa.w), cmb, cmi);
                    upd(b1, __float_as_uint(pb.w), cmb, cmi);
                }
                unsigned vmc = redux_maxu(cmb);
                unsigned cand = (cmb == vmc) ? cmi : 0xffffffffu;
                unsigned imc = redux_minu(cand);
                if (lane == 0) { sCV[sc] = vmc; sCI[sc] = imc; }
                upd(vmc, imc, bestb, besti);
            }
        }
        int par = k & 1;
        if (lane == 0) { sv[par][w] = bestb; si[par][w] = besti; }
        __syncthreads();
        unsigned v2 = sv[par][lane & 7], i2 = si[par][lane & 7];
        unsigned g  = redux_maxu(v2);
        unsigned c2 = (v2 == g) ? i2 : 0xffffffffu;
        unsigned io = redux_minu(c2);
        sel = inv[io];
    }
}

// ==================================================================
// bevscan: ball-query scan (blocks 0..127) + BEV bilinear (blocks 128..)
// ==================================================================
__global__ void __launch_bounds__(512) bevscan_kernel(const float* __restrict__ sf,
                                                      float* __restrict__ feats) {
    __shared__ float2 sx[1024], sy[1024], sz[1024];
    __shared__ int sidx[16][2][2][16];
    int tid = threadIdx.x;

    if (blockIdx.x >= SCANBLK) {
        int row = ((int)blockIdx.x - SCANBLK)*2 + (tid >> 8);
        int c = tid & 255;
        int b = row >> 11;
        float kx = g_kp[row*3+0], ky = g_kp[row*3+1];
        float xi = ((kx - 0.0f)     / 0.05f) / 8.0f;
        float yi = ((ky - (-40.0f)) / 0.05f) / 8.0f;
        int x0 = (int)floorf(xi); int x1 = x0 + 1;
        int y0 = (int)floorf(yi); int y1 = y0 + 1;
        x0 = min(max(x0, 0), WBEV-1); x1 = min(max(x1, 0), WBEV-1);
        y0 = min(max(y0, 0), HBEV-1); y1 = min(max(y1, 0), HBEV-1);
        float x0f = (float)x0, x1f = (float)x1, y0f = (float)y0, y1f = (float)y1;
        float wa = (x1f - xi)*(y1f - yi);
        float wb = (x1f - xi)*(yi - y0f);
        float wc = (xi - x0f)*(y1f - yi);
        float wd = (xi - x0f)*(yi - y0f);
        const float* ch = sf + ((size_t)b*CBEV + c)*HW;
        float Ia = __ldg(ch + y0*WBEV + x0);
        float Ib = __ldg(ch + y1*WBEV + x0);
        float Ic = __ldg(ch + y0*WBEV + x1);
        float Id = __ldg(ch + y1*WBEV + x1);
        feats[(size_t)row*288 + c] = Ia*wa + Ib*wb + Ic*wc + Id*wd;
        return;
    }

    int w = tid >> 5, lane = tid & 31;
    int row0 = blockIdx.x*32 + w*2;
    int b = row0 >> 11;
    const float4* P = g_pts + (size_t)b*NPTS;

    unsigned long long nkx[2], nky[2], nkz[2];
    #pragma unroll
    for (int kp = 0; kp < 2; kp++) {
        float kx = g_kp[(row0+kp)*3], ky = g_kp[(row0+kp)*3+1], kz = g_kp[(row0+kp)*3+2];
        nkx[kp] = pk2(-kx, -kx); nky[kp] = pk2(-ky, -ky); nkz[kp] = pk2(-kz, -kz);
    }
    unsigned lt  = (1u << lane) - 1u;
    unsigned lte = lt | (1u << lane);

    int c1[2] = {0,0}, c2[2] = {0,0};
    for (int base0 = 0; base0 < NPTS; base0 += 2048) {
        __syncthreads();
        #pragma unroll
        for (int i = 0; i < 2; i++) {
            int j = tid + i*512;
            float4 p0 = P[base0 + 2*j];
            float4 p1 = P[base0 + 2*j + 1];
            sx[j] = make_float2(p0.x, p1.x);
            sy[j] = make_float2(p0.y, p1.y);
            sz[j] = make_float2(p0.z, p1.z);
        }
        __syncthreads();
        if (c1[0] >= 16 && c2[0] >= 16 && c1[1] >= 16 && c2[1] >= 16) continue;
        for (int o32 = 0; o32 < 1024; o32 += 32) {
            float2 vx = sx[o32 + lane], vy = sy[o32 + lane], vz = sz[o32 + lane];
            unsigned long long px = pk2(vx.x, vx.y);
            unsigned long long py = pk2(vy.x, vy.y);
            unsigned long long pz = pk2(vz.x, vz.y);
            float da[2], db[2];
            #pragma unroll
            for (int kp = 0; kp < 2; kp++) {
                unsigned long long dx = addx2(px, nkx[kp]);
                unsigned long long dy = addx2(py, nky[kp]);
                unsigned long long dz = addx2(pz, nkz[kp]);
                unsigned long long d2 = addx2(addx2(mulx2(dx,dx), mulx2(dy,dy)), mulx2(dz,dz));
                upk2(d2, da[kp], db[kp]);
            }
            bool any = (da[0] < 4.0f) || (db[0] < 4.0f) || (da[1] < 4.0f) || (db[1] < 4.0f);
            if (__ballot_sync(FULLM, any)) {
                int gi = base0 + 2*(o32 + lane);
                #pragma unroll
                for (int kp = 0; kp < 2; kp++) {
                    bool v2a = da[kp] < 4.0f, v2b = db[kp] < 4.0f;
                    bool v1a = da[kp] < 1.0f, v1b = db[kp] < 1.0f;
                    unsigned m1e = __ballot_sync(FULLM, v1a);
                    unsigned m1o = __ballot_sync(FULLM, v1b);
                    unsigned m2e = __ballot_sync(FULLM, v2a);
                    unsigned m2o = __ballot_sync(FULLM, v2b);
                    if (c1[kp] < 16 && (m1e | m1o)) {
                        int re = __popc(m1e & lt)  + __popc(m1o & lt);
                        int ro = __popc(m1e & lte) + __popc(m1o & lt);
                        if (v1a && c1[kp] + re < 16) sidx[w][kp][0][c1[kp]+re] = gi;
                        if (v1b && c1[kp] + ro < 16) sidx[w][kp][0][c1[kp]+ro] = gi + 1;
                        c1[kp] = min(c1[kp] + __popc(m1e) + __popc(m1o), 16);
                    }
                    if (c2[kp] < 16 && (m2e | m2o)) {
                        int re = __popc(m2e & lt)  + __popc(m2o & lt);
                        int ro = __popc(m2e & lte) + __popc(m2o & lt);
                        if (v2a && c2[kp] + re < 16) sidx[w][kp][1][c2[kp]+re] = gi;
                        if (v2b && c2[kp] + ro < 16) sidx[w][kp][1][c2[kp]+ro] = gi + 1;
                        c2[kp] = min(c2[kp] + __popc(m2e) + __popc(m2o), 16);
                    }
                }
                if (c1[0] >= 16 && c2[0] >= 16 && c1[1] >= 16 && c2[1] >= 16) break;
            }
        }
    }
    __syncwarp();
    int rI = lane >> 4, s = lane & 15;
    #pragma unroll
    for (int kp = 0; kp < 2; kp++) {
        int row = row0 + kp;
        if (lane < 2) g_ballcnt[row*2 + lane] = lane ? c2[kp] : c1[kp];
        int cnt = rI ? c2[kp] : c1[kp];
        g_ballidx[row*32 + lane] = (s < cnt) ? sidx[w][kp][rI][s]
                                             : (cnt > 0 ? sidx[w][kp][rI][0] : 0);
    }
}

// ==================================================================
// mlpgemm: SA MLP + maxpool + GEMM [4,288]@[288,128] + BN + ReLU
// ==================================================================
__global__ void __launch_bounds__(128) mlpgemm_kernel(
        const float* __restrict__ w0, const float* __restrict__ bn0,
        const float* __restrict__ w1, const float* __restrict__ bn1,
        const float* __restrict__ fw, const float* __restrict__ fbn,
        float* __restrict__ feats, float* __restrict__ out) {
    __shared__ float sr[4*288];
    __shared__ float sw0[128];
    __shared__ float sw1[512];
    __shared__ float sb0s[32], sb0m[32], sb0b[32];
    __shared__ float sb1s[32], sb1m[32], sb1b[32];
    int tid = threadIdx.x;
    int row0 = blockIdx.x*4;
    int b = row0 >> 11;

    sw0[tid] = w0[tid];
    #pragma unroll
    for (int i = 0; i < 4; i++) sw1[tid + i*128] = w1[tid + i*128];
    if (tid < 32) {
        int br = tid >> 4, c = tid & 15;
        float g = bn0[br*64 + c], be = bn0[br*64+16+c], m = bn0[br*64+32+c], v = bn0[br*64+48+c];
        sb0s[tid] = g * (1.0f/sqrtf(v + 1e-5f)); sb0m[tid] = m; sb0b[tid] = be;
        g = bn1[br*64 + c]; be = bn1[br*64+16+c]; m = bn1[br*64+32+c]; v = bn1[br*64+48+c];
        sb1s[tid] = g * (1.0f/sqrtf(v + 1e-5f)); sb1m[tid] = m; sb1b[tid] = be;
    }
    #pragma unroll
    for (int r = 0; r < 4; r++) {
        #pragma unroll
        for (int h = 0; h < 2; h++)
            sr[r*288 + tid + h*128] = feats[(size_t)(row0 + r)*288 + tid + h*128];
    }
    __syncthreads();

    {
        int g = tid >> 4;
        int r = g >> 1, rI = g & 1, s = tid & 15;
        int row = row0 + r;
        float kx = g_kp[row*3], ky = g_kp[row*3+1], kz = g_kp[row*3+2];
        const float4* P = g_pts + (size_t)b*NPTS;
        int cnt = g_ballcnt[row*2 + rI];
        float gx = 0.f, gy = 0.f, gz = 0.f, gi = 0.f;
        if (cnt > 0) {
            int id = g_ballidx[row*32 + rI*16 + ((s < cnt) ? s : 0)];
            float4 p = P[id];
            gx = p.x - kx; gy = p.y - ky; gz = p.z - kz; gi = p.w;
        }
        const float* W0  = sw0  + rI*64;
        const float* W1  = sw1  + rI*256;
        const float* B0s = sb0s + rI*16; const float* B0m = sb0m + rI*16; const float* B0b = sb0b + rI*16;
        const float* B1s = sb1s + rI*16; const float* B1m = sb1m + rI*16; const float* B1b = sb1b + rI*16;

        float h1[16];
        #pragma unroll
        for (int c = 0; c < 16; c++) {
            float a = gx*W0[c] + gy*W0[16+c] + gz*W0[32+c] + gi*W0[48+c];
            h1[c] = fmaxf((a - B0m[c])*B0s[c] + B0b[c], 0.0f);
        }
        float h2[16];
        #pragma unroll
        for (int c = 0; c < 16; c++) {
            float a = 0.f;
            #pragma unroll
            for (int k = 0; k < 16; k++) a += h1[k]*W1[k*16 + c];
            h2[c] = fmaxf((a - B1m[c])*B1s[c] + B1b[c], 0.0f);
        }
        #pragma unroll
        for (int off = 8; off; off >>= 1) {
            #pragma unroll
            for (int c = 0; c < 16; c++)
                h2[c] = fmaxf(h2[c], __shfl_xor_sync(FULLM, h2[c], off));
        }
        if (s == 0) {
            #pragma unroll
            for (int c = 0; c < 16; c++) {
                sr[r*288 + 256 + rI*16 + c] = h2[c];
                feats[(size_t)row*288 + 256 + rI*16 + c] = h2[c];
            }
        }
    }
    __syncthreads();

    float acc[4] = {0.f, 0.f, 0.f, 0.f};
    for (int k = 0; k < 288; k++) {
        float wv = __ldg(fw + (size_t)k*128 + tid);
        #pragma unroll
        for (int r = 0; r < 4; r++) acc[r] += sr[r*288 + k] * wv;
    }
    float g = fbn[tid], be = fbn[128+tid], m = fbn[256+tid], v = fbn[384+tid];
    float sc = g * (1.0f/sqrtf(v + 1e-5f));
    #pragma unroll
    for (int r = 0; r < 4; r++)
        out[(size_t)(row0 + r)*128 + tid] = fmaxf((acc[r] - m)*sc + be, 0.f);
}

// ---------------- launch ----------------
extern "C" void kernel_launch(void* const* d_in, const int* in_sizes, int n_in,
                              void* d_out, int out_size) {
    const float* points = (const float*)d_in[0];
    const float* rng    = (const float*)d_in[1];
    const float* sf     = (const float*)d_in[2];
    const float* sa_w0  = (const float*)d_in[3];
    const float* sa_bn0 = (const float*)d_in[4];
    const float* sa_w1  = (const float*)d_in[5];
    const float* sa_bn1 = (const float*)d_in[6];
    const float* fw     = (const float*)d_in[7];
    const float* fbn    = (const float*)d_in[8];
    float* out = (float*)d_out;

    float* fused  = out;                                          // [4096,128]
    float* feats  = out + (size_t)NROWS*128;                      // [4096,288]
    float* coords = out + (size_t)NROWS*128 + (size_t)NROWS*288;  // [4096,4]

    const int FPS_SMEM = 131072 + 32768 + 16384;   // scmp + sD + inv = 176 KB
    cudaFuncSetAttribute(fps_kernel, cudaFuncAttributeMaxDynamicSharedMemorySize, FPS_SMEM);

    fps_kernel<<<64, 256, FPS_SMEM>>>(points, rng, coords);
    bevscan_kernel<<<SCANBLK + NROWS/2, 512>>>(sf, feats);
    mlpgemm_kernel<<<NROWS/4, 128>>>(sa_w0, sa_bn0, sa_w1, sa_bn1, fw, fbn, feats, fused);
}

// round 9
// speedup vs baseline: 1.5636x; 1.5636x over previous
#include <cuda_runtime.h>
#include <math.h>

#define NPTS   16384
#define BATCH  2
#define HBEV   200
#define WBEV   176
#define CBEV   256
#define HW     (HBEV*WBEV)
#define KTOT   2048
#define NROWS  (BATCH*KTOT)
#define CMPN   8192
#define FULLM  0xffffffffu
#define NCONS  142
#define NGRP   512

// ---------------- static device scratch ----------------
__device__ float4 g_pts[BATCH*NPTS];   // SoA points
__device__ float  g_kp[NROWS*3];       // keypoint coords
__device__ int    g_prog[6];           // per-band published keypoint count

// ---------------- packed f32x2 + redux helpers ----------------
__device__ __forceinline__ unsigned long long pk2(float lo, float hi) {
    unsigned long long r; asm("mov.b64 %0, {%1, %2};" : "=l"(r) : "f"(lo), "f"(hi)); return r;
}
__device__ __forceinline__ void upk2(unsigned long long v, float& lo, float& hi) {
    asm("mov.b64 {%0, %1}, %2;" : "=f"(lo), "=f"(hi) : "l"(v));
}
__device__ __forceinline__ unsigned long long addx2(unsigned long long a, unsigned long long b) {
    unsigned long long r; asm("add.rn.f32x2 %0, %1, %2;" : "=l"(r) : "l"(a), "l"(b)); return r;
}
__device__ __forceinline__ unsigned long long mulx2(unsigned long long a, unsigned long long b) {
    unsigned long long r; asm("mul.rn.f32x2 %0, %1, %2;" : "=l"(r) : "l"(a), "l"(b)); return r;
}
__device__ __forceinline__ unsigned redux_maxu(unsigned v) {
    unsigned r; asm("redux.sync.max.u32 %0, %1, 0xffffffff;" : "=r"(r) : "r"(v)); return r;
}
__device__ __forceinline__ unsigned redux_minu(unsigned v) {
    unsigned r; asm("redux.sync.min.u32 %0, %1, 0xffffffff;" : "=r"(r) : "r"(v)); return r;
}

// ---------------- prep: SoA points + progress reset ----------------
__global__ void __launch_bounds__(256) prep_kernel(const float* __restrict__ pts) {
    int i = blockIdx.x*256 + threadIdx.x;
    if (i < BATCH*NPTS) {
        const float* p = pts + (size_t)i*5;
        g_pts[i] = make_float4(p[1], p[2], p[3], p[4]);
    }
    if (i < 6) g_prog[i] = 0;
}

// ==================================================================
// FPS body — EXACT copy of the measured-best (R5) version,
// plus an every-8-keypoints progress publish by t0.
// ==================================================================
template<int P>
__device__ __forceinline__ void fps_body(int run, int b, int K, int kpbase, int M,
                                         float* __restrict__ coords_out,
                                         unsigned (*sv)[8], unsigned (*si)[8]) {
    extern __shared__ float4 scmp[];
    int t = threadIdx.x;
    int lane = t & 31, warp = t >> 5;

    unsigned long long Xn[P], Yn[P], Zn[P];   // negated coords
    float D[2*P];
    #pragma unroll
    for (int p = 0; p < P; p++) {
        float4 a = scmp[(2*p)*256 + t];
        float4 c = scmp[(2*p+1)*256 + t];
        Xn[p] = pk2(-a.x, -c.x); Yn[p] = pk2(-a.y, -c.y); Zn[p] = pk2(-a.z, -c.z);
        D[2*p]   = ((2*p)*256 + t   < M) ? 1e10f : -1.0f;
        D[2*p+1] = ((2*p+1)*256 + t < M) ? 1e10f : -1.0f;
    }

    int sel = 0;   // first valid point = compacted index 0
    for (int k = 0; ; k++) {
        float4 w = scmp[sel];                // LDS broadcast
        if (t == 0) {
            int r = kpbase + k;
            g_kp[r*3+0] = w.x; g_kp[r*3+1] = w.y; g_kp[r*3+2] = w.z;
            coords_out[r*4+0] = (float)b;
            coords_out[r*4+1] = w.x; coords_out[r*4+2] = w.y; coords_out[r*4+3] = w.z;
            if ((k & 7) == 7) {              // publish progress (fire-and-forget RED)
                __threadfence();
                atomicAdd(&g_prog[run], 8);
            }
        }
        if (k == K-1) break;

        unsigned long long wx = pk2(w.x, w.x);
        unsigned long long wy = pk2(w.y, w.y);
        unsigned long long wz = pk2(w.z, w.z);
        float bm[4] = {-1.f, -1.f, -1.f, -1.f};
        #pragma unroll
        for (int p = 0; p < P; p++) {
            unsigned long long dx = addx2(Xn[p], wx);   // (w-x): square == (x-w)^2 exactly
            unsigned long long dy = addx2(Yn[p], wy);
            unsigned long long dz = addx2(Zn[p], wz);
            unsigned long long d2 = addx2(addx2(mulx2(dx,dx), mulx2(dy,dy)), mulx2(dz,dz));
            float dl, dh; upk2(d2, dl, dh);
            float n0 = fminf(D[2*p],   dl); D[2*p]   = n0;
            float n1 = fminf(D[2*p+1], dh); D[2*p+1] = n1;
            bm[p & 3] = fmaxf(bm[p & 3], fmaxf(n0, n1));
        }
        float best = fmaxf(fmaxf(bm[0], bm[1]), fmaxf(bm[2], bm[3]));
        best = fmaxf(best, 0.0f);            // all-invalid thread: stays non-winner
        unsigned myidx = 0x7fffffffu;
        #pragma unroll
        for (int j = 2*P-1; j >= 0; j--)
            if (D[j] == best) myidx = (unsigned)(j*256 + t);   // smallest j wins

        unsigned u  = __float_as_uint(best); // d>=0 => bits order-isomorphic
        unsigned vm = redux_maxu(u);
        unsigned cand = (u == vm) ? myidx : 0x7fffffffu;
        unsigned im = redux_minu(cand);
        int par = k & 1;
        if (lane == 0) { sv[par][warp] = vm; si[par][warp] = im; }
        __syncthreads();
        unsigned v2 = sv[par][lane & 7];
        unsigned i2 = si[par][lane & 7];
        unsigned g  = redux_maxu(v2);
        unsigned c2 = (v2 == g) ? i2 : 0x7fffffffu;
        sel = (int)redux_minu(c2);
    }
}

// ==================================================================
// mega kernel: blocks 0..5 FPS producers, blocks 6..147 consumers
// (grid 148, 1 block/SM via smem -> all co-resident, no deadlock)
// ==================================================================
__global__ void __launch_bounds__(256,1) mega_kernel(
        const float* __restrict__ pts,  const float* __restrict__ rng,
        const float* __restrict__ sf,
        const float* __restrict__ w0,   const float* __restrict__ bn0,
        const float* __restrict__ w1,   const float* __restrict__ bn1,
        const float* __restrict__ fw,   const float* __restrict__ fbn,
        float* __restrict__ coords_out, float* __restrict__ feats,
        float* __restrict__ fused) {
    extern __shared__ float4 scmp[];
    // fps statics
    __shared__ unsigned sv[2][8], si[2][8];
    __shared__ int wsum[8];
    __shared__ int s_tot;
    // consumer statics
    __shared__ float2 sx[1024], sy[1024], sz[1024];
    __shared__ int   sidx8[8][2][16];
    __shared__ int   scnt8[8][2];
    __shared__ float sr[8*288];
    __shared__ float sp[2][8][128];
    __shared__ float sw0[128], sw1[512];
    __shared__ float sb0s[32], sb0m[32], sb0b[32];
    __shared__ float sb1s[32], sb1m[32], sb1b[32];
    __shared__ float skp[24];

    int t = threadIdx.x;
    int lane = t & 31, w = t >> 5;

    if (blockIdx.x < 6) {
        // ================= FPS producer =================
        int run = blockIdx.x, b = run/3, band = run - b*3;

        // stable band compaction: 64 points per thread (contiguous)
        const float4* R4 = (const float4*)(rng + (size_t)b*NPTS) + t*16;
        unsigned long long bits = 0; int cnt = 0;
        #pragma unroll
        for (int q = 0; q < 16; q++) {
            float4 r4 = R4[q];
            float rr[4] = {r4.x, r4.y, r4.z, r4.w};
            #pragma unroll
            for (int u = 0; u < 4; u++) {
                float r = rr[u];
                bool sh = (r > 0.0f) && (r < 25.0f);
                bool lg = (r > 45.0f);
                bool v = (band == 0) ? sh : ((band == 2) ? lg : (!lg && !sh));
                if (v) { bits |= (1ull << (q*4+u)); cnt++; }
            }
        }
        int inc = cnt;
        #pragma unroll
        for (int off = 1; off < 32; off <<= 1) {
            int o = __shfl_up_sync(FULLM, inc, off);
            if (lane >= off) inc += o;
        }
        if (lane == 31) wsum[w] = inc;
        __syncthreads();
        if (w == 0 && lane < 8) {
            int v = wsum[lane];
            #pragma unroll
            for (int off = 1; off < 8; off <<= 1) {
                int o = __shfl_up_sync(0xffu, v, off);
                if (lane >= off) v += o;
            }
            wsum[lane] = v;
            if (lane == 7) s_tot = v;
        }
        __syncthreads();
        int off0 = inc - cnt + (w ? wsum[w-1] : 0);
        const float* PP = pts + (size_t)b*NPTS*5;
        for (int u = 0; u < 64; u++) {
            if ((bits >> u) & 1ull) {
                if (off0 < CMPN) {
                    const float* p = PP + (size_t)(t*64 + u)*5;
                    scmp[off0] = make_float4(p[1], p[2], p[3], p[4]);
                }
                off0++;
            }
        }
        int M = min(s_tot, CMPN);
        for (int i = M + t; i < CMPN; i += 256)
            scmp[i] = make_float4(1e15f, 1e15f, 1e15f, 0.f);
        __syncthreads();

        int K = (band == 0) ? 1024 : 512;
        int kpbase = b*KTOT + (band==0 ? 0 : (band==1 ? 1024 : 1536));
        int P = min(16, ((M + 1023) >> 10) * 2);   // even, 512*P >= M
        switch (P) {
            case 2:  fps_body<2>(run, b, K, kpbase, M, coords_out, sv, si); break;
            case 4:  fps_body<4>(run, b, K, kpbase, M, coords_out, sv, si); break;
            case 6:  fps_body<6>(run, b, K, kpbase, M, coords_out, sv, si); break;
            case 8:  fps_body<8>(run, b, K, kpbase, M, coords_out, sv, si); break;
            case 10: fps_body<10>(run, b, K, kpbase, M, coords_out, sv, si); break;
            case 12: fps_body<12>(run, b, K, kpbase, M, coords_out, sv, si); break;
            case 14: fps_body<14>(run, b, K, kpbase, M, coords_out, sv, si); break;
            default: fps_body<16>(run, b, K, kpbase, M, coords_out, sv, si); break;
        }
        return;
    }

    // ================= consumer: 8-row groups =================
    int cb = (int)blockIdx.x - 6;

    // load small weights once
    if (t < 128) sw0[t] = w0[t];
    sw1[t] = w1[t]; sw1[t + 256] = w1[t + 256];
    if (t < 32) {
        int br = t >> 4, c = t & 15;
        float g = bn0[br*64 + c], be = bn0[br*64+16+c], m = bn0[br*64+32+c], v = bn0[br*64+48+c];
        sb0s[t] = g * (1.0f/sqrtf(v + 1e-5f)); sb0m[t] = m; sb0b[t] = be;
        g = bn1[br*64 + c]; be = bn1[br*64+16+c]; m = bn1[br*64+32+c]; v = bn1[br*64+48+c];
        sb1s[t] = g * (1.0f/sqrtf(v + 1e-5f)); sb1m[t] = m; sb1b[t] = be;
    }

    for (int g = cb; g < NGRP; g += NCONS) {
        int row0 = g*8;
        int b = row0 >> 11, off = row0 & 2047;
        int band = (off < 1024) ? 0 : ((off < 1536) ? 1 : 2);
        int k0 = off - ((band == 0) ? 0 : ((band == 1) ? 1024 : 1536));
        int run = b*3 + band;
        const float4* Pp = g_pts + (size_t)b*NPTS;

        // wait until the 8 keypoints of this group exist
        if (t == 0) {
            while (*((volatile int*)&g_prog[run]) < k0 + 8) __nanosleep(256);
        }
        __syncthreads();
        if (t < 24) skp[t] = __ldcg(&g_kp[row0*3 + t]);
        __syncthreads();

        // ---- phase A: BEV bilinear, direct CHW gather (1 channel/thread) ----
        #pragma unroll 1
        for (int r = 0; r < 8; r++) {
            float kx = skp[r*3], ky = skp[r*3+1];
            float xi = ((kx - 0.0f)     / 0.05f) / 8.0f;
            float yi = ((ky - (-40.0f)) / 0.05f) / 8.0f;
            int x0 = (int)floorf(xi); int x1 = x0 + 1;
            int y0 = (int)floorf(yi); int y1 = y0 + 1;
            x0 = min(max(x0, 0), WBEV-1); x1 = min(max(x1, 0), WBEV-1);
            y0 = min(max(y0, 0), HBEV-1); y1 = min(max(y1, 0), HBEV-1);
            float x0f = (float)x0, x1f = (float)x1, y0f = (float)y0, y1f = (float)y1;
            float wa = (x1f - xi)*(y1f - yi);
            float wb = (x1f - xi)*(yi - y0f);
            float wc = (xi - x0f)*(y1f - yi);
            float wd = (xi - x0f)*(yi - y0f);
            const float* ch = sf + ((size_t)b*CBEV + t)*HW;
            float Ia = __ldg(ch + y0*WBEV + x0);
            float Ib = __ldg(ch + y1*WBEV + x0);
            float Ic = __ldg(ch + y0*WBEV + x1);
            float Id = __ldg(ch + y1*WBEV + x1);
            float val = Ia*wa + Ib*wb + Ic*wc + Id*wd;
            sr[r*288 + t] = val;
            feats[(size_t)(row0 + r)*288 + t] = val;
        }

        // ---- phase B: ball-query scan, 1 row per warp, shared tiles ----
        {
            float kx = skp[w*3], ky = skp[w*3+1], kz = skp[w*3+2];
            unsigned long long nkx = pk2(-kx, -kx), nky = pk2(-ky, -ky), nkz = pk2(-kz, -kz);
            unsigned lt  = (1u << lane) - 1u;
            unsigned lte = lt | (1u << lane);
            int c1 = 0, c2 = 0;
            for (int base0 = 0; base0 < NPTS; base0 += 2048) {
                __syncthreads();
                #pragma unroll
                for (int i2 = 0; i2 < 4; i2++) {
                    int j = t + i2*256;
                    float4 p0 = Pp[base0 + 2*j];
                    float4 p1 = Pp[base0 + 2*j + 1];
                    sx[j] = make_float2(p0.x, p1.x);
                    sy[j] = make_float2(p0.y, p1.y);
                    sz[j] = make_float2(p0.z, p1.z);
                }
                __syncthreads();
                if (c1 >= 16 && c2 >= 16) continue;
                for (int o32 = 0; o32 < 1024; o32 += 32) {
                    float2 vx = sx[o32 + lane], vy = sy[o32 + lane], vz = sz[o32 + lane];
                    unsigned long long dx = addx2(pk2(vx.x, vx.y), nkx);
                    unsigned long long dy = addx2(pk2(vy.x, vy.y), nky);
                    unsigned long long dz = addx2(pk2(vz.x, vz.y), nkz);
                    unsigned long long d2 = addx2(addx2(mulx2(dx,dx), mulx2(dy,dy)), mulx2(dz,dz));
                    float da, db; upk2(d2, da, db);
                    bool v2a = da < 4.0f, v2b = db < 4.0f;
                    if (__ballot_sync(FULLM, v2a || v2b)) {
                        bool v1a = da < 1.0f, v1b = db < 1.0f;
                        unsigned m1e = __ballot_sync(FULLM, v1a);
                        unsigned m1o = __ballot_sync(FULLM, v1b);
                        unsigned m2e = __ballot_sync(FULLM, v2a);
                        unsigned m2o = __ballot_sync(FULLM, v2b);
                        int gi = base0 + 2*(o32 + lane);
                        if (c1 < 16 && (m1e | m1o)) {
                            int re = __popc(m1e & lt)  + __popc(m1o & lt);
                            int ro = __popc(m1e & lte) + __popc(m1o & lt);
                            if (v1a && c1 + re < 16) sidx8[w][0][c1+re] = gi;
                            if (v1b && c1 + ro < 16) sidx8[w][0][c1+ro] = gi + 1;
                            c1 = min(c1 + __popc(m1e) + __popc(m1o), 16);
                        }
                        if (c2 < 16 && (m2e | m2o)) {
                            int re = __popc(m2e & lt)  + __popc(m2o & lt);
                            int ro = __popc(m2e & lte) + __popc(m2o & lt);
                            if (v2a && c2 + re < 16) sidx8[w][1][c2+re] = gi;
                            if (v2b && c2 + ro < 16) sidx8[w][1][c2+ro] = gi + 1;
                            c2 = min(c2 + __popc(m2e) + __popc(m2o), 16);
                        }
                        if (c1 >= 16 && c2 >= 16) break;
                    }
                }
            }
            __syncwarp();
            if (lane < 2) scnt8[w][lane] = lane ? c2 : c1;
        }
        __syncthreads();

        // ---- phase C: SA MLP + maxpool (16 groups of 16 threads) ----
        {
            int g16 = t >> 4, s = t & 15;
            int r = g16 >> 1, rI = g16 & 1;
            int row = row0 + r;
            float kx = skp[r*3], ky = skp[r*3+1], kz = skp[r*3+2];
            int cnt = scnt8[r][rI];
            float gx = 0.f, gy = 0.f, gz = 0.f, gi = 0.f;
            if (cnt > 0) {
                int id = sidx8[r][rI][(s < cnt) ? s : 0];
                float4 p = Pp[id];
                gx = p.x - kx; gy = p.y - ky; gz = p.z - kz; gi = p.w;
            }
            const float* W0  = sw0  + rI*64;
            const float* W1  = sw1  + rI*256;
            const float* B0s = sb0s + rI*16; const float* B0m = sb0m + rI*16; const float* B0b = sb0b + rI*16;
            const float* B1s = sb1s + rI*16; const float* B1m = sb1m + rI*16; const float* B1b = sb1b + rI*16;

            float h1[16];
            #pragma unroll
            for (int c = 0; c < 16; c++) {
                float a = gx*W0[c] + gy*W0[16+c] + gz*W0[32+c] + gi*W0[48+c];
                h1[c] = fmaxf((a - B0m[c])*B0s[c] + B0b[c], 0.0f);
            }
            float h2[16];
            #pragma unroll
            for (int c = 0; c < 16; c++) {
                float a = 0.f;
                #pragma unroll
                for (int k = 0; k < 16; k++) a += h1[k]*W1[k*16 + c];
                h2[c] = fmaxf((a - B1m[c])*B1s[c] + B1b[c], 0.0f);
            }
            #pragma unroll
            for (int offp = 8; offp; offp >>= 1) {
                #pragma unroll
                for (int c = 0; c < 16; c++)
                    h2[c] = fmaxf(h2[c], __shfl_xor_sync(FULLM, h2[c], offp));
            }
            if (s == 0) {
                #pragma unroll
                for (int c = 0; c < 16; c++) {
                    sr[r*288 + 256 + rI*16 + c] = h2[c];
                    feats[(size_t)row*288 + 256 + rI*16 + c] = h2[c];
                }
            }
        }
        __syncthreads();

        // ---- phase D: GEMM [8,288]@[288,128], split-k halves ----
        {
            int half = t >> 7, outc = t & 127;
            float acc[8] = {0.f,0.f,0.f,0.f,0.f,0.f,0.f,0.f};
            int kb = half*144;
            for (int k2 = kb; k2 < kb + 144; k2++) {
                float wv = __ldg(fw + (size_t)k2*128 + outc);
                #pragma unroll
                for (int r = 0; r < 8; r++) acc[r] += sr[r*288 + k2] * wv;
            }
            #pragma unroll
            for (int r = 0; r < 8; r++) sp[half][r][outc] = acc[r];
        }
        __syncthreads();
        if (t < 128) {
            int outc = t;
            float gg = fbn[outc], be = fbn[128+outc], mm = fbn[256+outc], vv = fbn[384+outc];
            float sc2 = gg * (1.0f/sqrtf(vv + 1e-5f));
            #pragma unroll
            for (int r = 0; r < 8; r++) {
                float a = sp[0][r][outc] + sp[1][r][outc];
                fused[(size_t)(row0 + r)*128 + outc] = fmaxf((a - mm)*sc2 + be, 0.f);
            }
        }
        __syncthreads();
    }
}

// ---------------- launch ----------------
extern "C" void kernel_launch(void* const* d_in, const int* in_sizes, int n_in,
                              void* d_out, int out_size) {
    const float* points = (const float*)d_in[0];
    const float* rng    = (const float*)d_in[1];
    const float* sf     = (const float*)d_in[2];
    const float* sa_w0  = (const float*)d_in[3];
    const float* sa_bn0 = (const float*)d_in[4];
    const float* sa_w1  = (const float*)d_in[5];
    const float* sa_bn1 = (const float*)d_in[6];
    const float* fw     = (const float*)d_in[7];
    const float* fbn    = (const float*)d_in[8];
    float* out = (float*)d_out;

    float* fused  = out;                                          // [4096,128]
    float* feats  = out + (size_t)NROWS*128;                      // [4096,288]
    float* coords = out + (size_t)NROWS*128 + (size_t)NROWS*288;  // [4096,4]

    const int FPS_SMEM = CMPN * (int)sizeof(float4);   // 128 KB dynamic
    cudaFuncSetAttribute(mega_kernel, cudaFuncAttributeMaxDynamicSharedMemorySize, FPS_SMEM);

    prep_kernel<<<BATCH*NPTS/256, 256>>>(points);
    mega_kernel<<<6 + NCONS, 256, FPS_SMEM>>>(points, rng, sf,
                                              sa_w0, sa_bn0, sa_w1, sa_bn1,
                                              fw, fbn, coords, feats, fused);
}

// round 10
// speedup vs baseline: 1.8538x; 1.1856x over previous
#include <cuda_runtime.h>
#include <math.h>

#define NPTS   16384
#define BATCH  2
#define HBEV   200
#define WBEV   176
#define CBEV   256
#define HW     (HBEV*WBEV)
#define KTOT   2048
#define NROWS  (BATCH*KTOT)
#define CMPN   8192
#define FULLM  0xffffffffu
#define SCANBLK 128

// ---------------- static device scratch ----------------
__device__ float4 g_pts[BATCH*NPTS];       // SoA points: x,y,z,intensity
__device__ float  g_kp[NROWS*3];           // keypoint coords
__device__ int    g_ballidx[NROWS*32];     // [row][2][16] neighbor indices
__device__ int    g_ballcnt[NROWS*2];      // [row][2] capped counts

// ---------------- packed f32x2 + redux helpers ----------------
__device__ __forceinline__ unsigned long long pk2(float lo, float hi) {
    unsigned long long r; asm("mov.b64 %0, {%1, %2};" : "=l"(r) : "f"(lo), "f"(hi)); return r;
}
__device__ __forceinline__ void upk2(unsigned long long v, float& lo, float& hi) {
    asm("mov.b64 {%0, %1}, %2;" : "=f"(lo), "=f"(hi) : "l"(v));
}
__device__ __forceinline__ unsigned long long addx2(unsigned long long a, unsigned long long b) {
    unsigned long long r; asm("add.rn.f32x2 %0, %1, %2;" : "=l"(r) : "l"(a), "l"(b)); return r;
}
__device__ __forceinline__ unsigned long long mulx2(unsigned long long a, unsigned long long b) {
    unsigned long long r; asm("mul.rn.f32x2 %0, %1, %2;" : "=l"(r) : "l"(a), "l"(b)); return r;
}
__device__ __forceinline__ unsigned redux_maxu(unsigned v) {
    unsigned r; asm("redux.sync.max.u32 %0, %1, 0xffffffff;" : "=r"(r) : "r"(v)); return r;
}
__device__ __forceinline__ unsigned redux_minu(unsigned v) {
    unsigned r; asm("redux.sync.min.u32 %0, %1, 0xffffffff;" : "=r"(r) : "r"(v)); return r;
}

// ==================================================================
// FPS: compaction + sampling (blocks 0..5) + SoA prep (blocks 6..63)
// 512 threads (16 warps) for latency hiding; R5's proven redux tail.
// ==================================================================
template<int P>
__device__ __forceinline__ void fps_body(int b, int K, int kpbase, int M,
                                         float* __restrict__ coords_out,
                                         unsigned (*sv)[16], unsigned (*si)[16]) {
    extern __shared__ float4 scmp[];
    int t = threadIdx.x;
    int lane = t & 31, warp = t >> 5;

    unsigned long long Xn[P], Yn[P], Zn[P];   // negated coords
    float D[2*P];
    #pragma unroll
    for (int p = 0; p < P; p++) {
        float4 a = scmp[(2*p)*512 + t];
        float4 c = scmp[(2*p+1)*512 + t];
        Xn[p] = pk2(-a.x, -c.x); Yn[p] = pk2(-a.y, -c.y); Zn[p] = pk2(-a.z, -c.z);
        D[2*p]   = ((2*p)*512 + t   < M) ? 1e10f : -1.0f;
        D[2*p+1] = ((2*p+1)*512 + t < M) ? 1e10f : -1.0f;
    }

    int sel = 0;   // first valid point = compacted index 0
    for (int k = 0; ; k++) {
        float4 w = scmp[sel];                // LDS broadcast
        if (t == 0) {
            int r = kpbase + k;
            g_kp[r*3+0] = w.x; g_kp[r*3+1] = w.y; g_kp[r*3+2] = w.z;
            coords_out[r*4+0] = (float)b;
            coords_out[r*4+1] = w.x; coords_out[r*4+2] = w.y; coords_out[r*4+3] = w.z;
        }
        if (k == K-1) break;

        unsigned long long wx = pk2(w.x, w.x);
        unsigned long long wy = pk2(w.y, w.y);
        unsigned long long wz = pk2(w.z, w.z);
        float bm[4] = {-1.f, -1.f, -1.f, -1.f};
        #pragma unroll
        for (int p = 0; p < P; p++) {
            unsigned long long dx = addx2(Xn[p], wx);   // (w-x): square == (x-w)^2 exactly
            unsigned long long dy = addx2(Yn[p], wy);
            unsigned long long dz = addx2(Zn[p], wz);
            unsigned long long d2 = addx2(addx2(mulx2(dx,dx), mulx2(dy,dy)), mulx2(dz,dz));
            float dl, dh; upk2(d2, dl, dh);
            float n0 = fminf(D[2*p],   dl); D[2*p]   = n0;
            float n1 = fminf(D[2*p+1], dh); D[2*p+1] = n1;
            bm[p & 3] = fmaxf(bm[p & 3], fmaxf(n0, n1));
        }
        float best = fmaxf(fmaxf(bm[0], bm[1]), fmaxf(bm[2], bm[3]));
        best = fmaxf(best, 0.0f);            // all-invalid thread: stays non-winner
        unsigned myidx = 0x7fffffffu;
        #pragma unroll
        for (int j = 2*P-1; j >= 0; j--)
            if (D[j] == best) myidx = (unsigned)(j*512 + t);   // smallest j wins

        unsigned u  = __float_as_uint(best); // d>=0 => bits order-isomorphic
        unsigned vm = redux_maxu(u);
        unsigned cand = (u == vm) ? myidx : 0x7fffffffu;
        unsigned im = redux_minu(cand);
        int par = k & 1;
        if (lane == 0) { sv[par][warp] = vm; si[par][warp] = im; }
        __syncthreads();
        unsigned v2 = sv[par][lane & 15];
        unsigned i2 = si[par][lane & 15];
        unsigned g  = redux_maxu(v2);
        unsigned c2 = (v2 == g) ? i2 : 0x7fffffffu;
        sel = (int)redux_minu(c2);
    }
}

__global__ void __launch_bounds__(512,1) fps_kernel(const float* __restrict__ pts,
                                                    const float* __restrict__ rng,
                                                    float* __restrict__ coords_out) {
    extern __shared__ float4 scmp[];
    __shared__ unsigned sv[2][16], si[2][16];
    __shared__ int wsum[16];
    __shared__ int s_tot;

    int t = threadIdx.x;
    if (blockIdx.x >= 6) {
        // ---- SoA prep on otherwise-idle SMs ----
        for (int i = ((int)blockIdx.x - 6)*512 + t; i < BATCH*NPTS; i += 58*512) {
            const float* p = pts + (size_t)i*5;
            g_pts[i] = make_float4(p[1], p[2], p[3], p[4]);
        }
        return;
    }

    int run = blockIdx.x, b = run/3, band = run - b*3;
    int lane = t & 31, warp = t >> 5;

    // ---- stable band compaction: 32 points per thread (contiguous) ----
    const float4* R4 = (const float4*)(rng + (size_t)b*NPTS) + t*8;
    unsigned bits = 0; int cnt = 0;
    #pragma unroll
    for (int q = 0; q < 8; q++) {
        float4 r4 = R4[q];
        float rr[4] = {r4.x, r4.y, r4.z, r4.w};
        #pragma unroll
        for (int u = 0; u < 4; u++) {
            float r = rr[u];
            bool sh = (r > 0.0f) && (r < 25.0f);
            bool lg = (r > 45.0f);
            bool v = (band == 0) ? sh : ((band == 2) ? lg : (!lg && !sh));
            if (v) { bits |= (1u << (q*4+u)); cnt++; }
        }
    }
    int inc = cnt;
    #pragma unroll
    for (int off = 1; off < 32; off <<= 1) {
        int o = __shfl_up_sync(FULLM, inc, off);
        if (lane >= off) inc += o;
    }
    if (lane == 31) wsum[warp] = inc;
    __syncthreads();
    if (warp == 0 && lane < 16) {
        int v = wsum[lane];
        #pragma unroll
        for (int off = 1; off < 16; off <<= 1) {
            int o = __shfl_up_sync(0xffffu, v, off);
            if (lane >= off) v += o;
        }
        wsum[lane] = v;
        if (lane == 15) s_tot = v;
    }
    __syncthreads();
    int off0 = inc - cnt + (warp ? wsum[warp-1] : 0);
    const float* PP = pts + (size_t)b*NPTS*5;
    for (int u = 0; u < 32; u++) {
        if ((bits >> u) & 1u) {
            if (off0 < CMPN) {
                const float* p = PP + (size_t)(t*32 + u)*5;
                scmp[off0] = make_float4(p[1], p[2], p[3], p[4]);
            }
            off0++;
        }
    }
    int M = min(s_tot, CMPN);
    for (int i = M + t; i < CMPN; i += 512)
        scmp[i] = make_float4(1e15f, 1e15f, 1e15f, 0.f);
    __syncthreads();

    // ---- FPS dispatch sized to the band population (slot = 1024 pts) ----
    int K = (band == 0) ? 1024 : 512;
    int kpbase = b*KTOT + (band==0 ? 0 : (band==1 ? 1024 : 1536));
    int P = min(8, (M + 1023) >> 10);
    switch (P) {
        case 1:  fps_body<1>(b, K, kpbase, M, coords_out, sv, si); break;
        case 2:  fps_body<2>(b, K, kpbase, M, coords_out, sv, si); break;
        case 3:  fps_body<3>(b, K, kpbase, M, coords_out, sv, si); break;
        case 4:  fps_body<4>(b, K, kpbase, M, coords_out, sv, si); break;
        case 5:  fps_body<5>(b, K, kpbase, M, coords_out, sv, si); break;
        case 6:  fps_body<6>(b, K, kpbase, M, coords_out, sv, si); break;
        case 7:  fps_body<7>(b, K, kpbase, M, coords_out, sv, si); break;
        default: fps_body<8>(b, K, kpbase, M, coords_out, sv, si); break;
    }
}

// ==================================================================
// bevscan: ball-query scan (blocks 0..127) + BEV bilinear (blocks 128..)
// ==================================================================
__global__ void __launch_bounds__(512) bevscan_kernel(const float* __restrict__ sf,
                                                      float* __restrict__ feats) {
    __shared__ float2 sx[1024], sy[1024], sz[1024];
    __shared__ int sidx[16][2][2][16];
    int tid = threadIdx.x;

    if (blockIdx.x >= SCANBLK) {
        int row = ((int)blockIdx.x - SCANBLK)*2 + (tid >> 8);
        int c = tid & 255;
        int b = row >> 11;
        float kx = g_kp[row*3+0], ky = g_kp[row*3+1];
        float xi = ((kx - 0.0f)     / 0.05f) / 8.0f;
        float yi = ((ky - (-40.0f)) / 0.05f) / 8.0f;
        int x0 = (int)floorf(xi); int x1 = x0 + 1;
        int y0 = (int)floorf(yi); int y1 = y0 + 1;
        x0 = min(max(x0, 0), WBEV-1); x1 = min(max(x1, 0), WBEV-1);
        y0 = min(max(y0, 0), HBEV-1); y1 = min(max(y1, 0), HBEV-1);
        float x0f = (float)x0, x1f = (float)x1, y0f = (float)y0, y1f = (float)y1;
        float wa = (x1f - xi)*(y1f - yi);
        float wb = (x1f - xi)*(yi - y0f);
        float wc = (xi - x0f)*(y1f - yi);
        float wd = (xi - x0f)*(yi - y0f);
        const float* ch = sf + ((size_t)b*CBEV + c)*HW;
        float Ia = __ldg(ch + y0*WBEV + x0);
        float Ib = __ldg(ch + y1*WBEV + x0);
        float Ic = __ldg(ch + y0*WBEV + x1);
        float Id = __ldg(ch + y1*WBEV + x1);
        feats[(size_t)row*288 + c] = Ia*wa + Ib*wb + Ic*wc + Id*wd;
        return;
    }

    int w = tid >> 5, lane = tid & 31;
    int row0 = blockIdx.x*32 + w*2;
    int b = row0 >> 11;
    const float4* P = g_pts + (size_t)b*NPTS;

    unsigned long long nkx[2], nky[2], nkz[2];
    #pragma unroll
    for (int kp = 0; kp < 2; kp++) {
        float kx = g_kp[(row0+kp)*3], ky = g_kp[(row0+kp)*3+1], kz = g_kp[(row0+kp)*3+2];
        nkx[kp] = pk2(-kx, -kx); nky[kp] = pk2(-ky, -ky); nkz[kp] = pk2(-kz, -kz);
    }
    unsigned lt  = (1u << lane) - 1u;
    unsigned lte = lt | (1u << lane);

    int c1[2] = {0,0}, c2[2] = {0,0};
    for (int base0 = 0; base0 < NPTS; base0 += 2048) {
        __syncthreads();
        #pragma unroll
        for (int i = 0; i < 2; i++) {
            int j = tid + i*512;
            float4 p0 = P[base0 + 2*j];
            float4 p1 = P[base0 + 2*j + 1];
            sx[j] = make_float2(p0.x, p1.x);
            sy[j] = make_float2(p0.y, p1.y);
            sz[j] = make_float2(p0.z, p1.z);
        }
        __syncthreads();
        if (c1[0] >= 16 && c2[0] >= 16 && c1[1] >= 16 && c2[1] >= 16) continue;
        for (int o32 = 0; o32 < 1024; o32 += 32) {
            float2 vx = sx[o32 + lane], vy = sy[o32 + lane], vz = sz[o32 + lane];
            unsigned long long px = pk2(vx.x, vx.y);
            unsigned long long py = pk2(vy.x, vy.y);
            unsigned long long pz = pk2(vz.x, vz.y);
            float da[2], db[2];
            #pragma unroll
            for (int kp = 0; kp < 2; kp++) {
                unsigned long long dx = addx2(px, nkx[kp]);
                unsigned long long dy = addx2(py, nky[kp]);
                unsigned long long dz = addx2(pz, nkz[kp]);
                unsigned long long d2 = addx2(addx2(mulx2(dx,dx), mulx2(dy,dy)), mulx2(dz,dz));
                upk2(d2, da[kp], db[kp]);
            }
            bool any = (da[0] < 4.0f) || (db[0] < 4.0f) || (da[1] < 4.0f) || (db[1] < 4.0f);
            if (__ballot_sync(FULLM, any)) {
                int gi = base0 + 2*(o32 + lane);
                #pragma unroll
                for (int kp = 0; kp < 2; kp++) {
                    bool v2a = da[kp] < 4.0f, v2b = db[kp] < 4.0f;
                    bool v1a = da[kp] < 1.0f, v1b = db[kp] < 1.0f;
                    unsigned m1e = __ballot_sync(FULLM, v1a);
                    unsigned m1o = __ballot_sync(FULLM, v1b);
                    unsigned m2e = __ballot_sync(FULLM, v2a);
                    unsigned m2o = __ballot_sync(FULLM, v2b);
                    if (c1[kp] < 16 && (m1e | m1o)) {
                        int re = __popc(m1e & lt)  + __popc(m1o & lt);
                        int ro = __popc(m1e & lte) + __popc(m1o & lt);
                        if (v1a && c1[kp] + re < 16) sidx[w][kp][0][c1[kp]+re] = gi;
                        if (v1b && c1[kp] + ro < 16) sidx[w][kp][0][c1[kp]+ro] = gi + 1;
                        c1[kp] = min(c1[kp] + __popc(m1e) + __popc(m1o), 16);
                    }
                    if (c2[kp] < 16 && (m2e | m2o)) {
                        int re = __popc(m2e & lt)  + __popc(m2o & lt);
                        int ro = __popc(m2e & lte) + __popc(m2o & lt);
                        if (v2a && c2[kp] + re < 16) sidx[w][kp][1][c2[kp]+re] = gi;
                        if (v2b && c2[kp] + ro < 16) sidx[w][kp][1][c2[kp]+ro] = gi + 1;
                        c2[kp] = min(c2[kp] + __popc(m2e) + __popc(m2o), 16);
                    }
                }
                if (c1[0] >= 16 && c2[0] >= 16 && c1[1] >= 16 && c2[1] >= 16) break;
            }
        }
    }
    __syncwarp();
    int rI = lane >> 4, s = lane & 15;
    #pragma unroll
    for (int kp = 0; kp < 2; kp++) {
        int row = row0 + kp;
        if (lane < 2) g_ballcnt[row*2 + lane] = lane ? c2[kp] : c1[kp];
        int cnt = rI ? c2[kp] : c1[kp];
        g_ballidx[row*32 + lane] = (s < cnt) ? sidx[w][kp][rI][s]
                                             : (cnt > 0 ? sidx[w][kp][rI][0] : 0);
    }
}

// ==================================================================
// mlpgemm: SA MLP + maxpool + split-k GEMM [8,288]@[288,128] + BN + ReLU
// 256 threads, 8 rows per block, 512 blocks (2x resident warps vs R5)
// ==================================================================
__global__ void __launch_bounds__(256) mlpgemm_kernel(
        const float* __restrict__ w0, const float* __restrict__ bn0,
        const float* __restrict__ w1, const float* __restrict__ bn1,
        const float* __restrict__ fw, const float* __restrict__ fbn,
        float* __restrict__ feats, float* __restrict__ out) {
    __shared__ float sr[8*288];
    __shared__ float sp[2][8][128];
    __shared__ float sw0[128];
    __shared__ float sw1[512];
    __shared__ float sb0s[32], sb0m[32], sb0b[32];
    __shared__ float sb1s[32], sb1m[32], sb1b[32];
    int tid = threadIdx.x;
    int row0 = blockIdx.x*8;
    int b = row0 >> 11;

    if (tid < 128) sw0[tid] = w0[tid];
    sw1[tid] = w1[tid]; sw1[tid + 256] = w1[tid + 256];
    if (tid < 32) {
        int br = tid >> 4, c = tid & 15;
        float g = bn0[br*64 + c], be = bn0[br*64+16+c], m = bn0[br*64+32+c], v = bn0[br*64+48+c];
        sb0s[tid] = g * (1.0f/sqrtf(v + 1e-5f)); sb0m[tid] = m; sb0b[tid] = be;
        g = bn1[br*64 + c]; be = bn1[br*64+16+c]; m = bn1[br*64+32+c]; v = bn1[br*64+48+c];
        sb1s[tid] = g * (1.0f/sqrtf(v + 1e-5f)); sb1m[tid] = m; sb1b[tid] = be;
    }
    // load bev features (channels 0..255) for the 8 rows
    if (tid < 256) {
        #pragma unroll
        for (int r = 0; r < 8; r++)
            sr[r*288 + tid] = feats[(size_t)(row0 + r)*288 + tid];
    }
    __syncthreads();

    // ---- SA MLP + maxpool (16 groups of 16 threads) ----
    {
        int g16 = tid >> 4, s = tid & 15;
        int r = g16 >> 1, rI = g16 & 1;
        int row = row0 + r;
        float kx = g_kp[row*3], ky = g_kp[row*3+1], kz = g_kp[row*3+2];
        const float4* P = g_pts + (size_t)b*NPTS;
        int cnt = g_ballcnt[row*2 + rI];
        float gx = 0.f, gy = 0.f, gz = 0.f, gi = 0.f;
        if (cnt > 0) {
            int id = g_ballidx[row*32 + rI*16 + ((s < cnt) ? s : 0)];
            float4 p = P[id];
            gx = p.x - kx; gy = p.y - ky; gz = p.z - kz; gi = p.w;
        }
        const float* W0  = sw0  + rI*64;
        const float* W1  = sw1  + rI*256;
        const float* B0s = sb0s + rI*16; const float* B0m = sb0m + rI*16; const float* B0b = sb0b + rI*16;
        const float* B1s = sb1s + rI*16; const float* B1m = sb1m + rI*16; const float* B1b = sb1b + rI*16;

        float h1[16];
        #pragma unroll
        for (int c = 0; c < 16; c++) {
            float a = gx*W0[c] + gy*W0[16+c] + gz*W0[32+c] + gi*W0[48+c];
            h1[c] = fmaxf((a - B0m[c])*B0s[c] + B0b[c], 0.0f);
        }
        float h2[16];
        #pragma unroll
        for (int c = 0; c < 16; c++) {
            float a = 0.f;
            #pragma unroll
            for (int k = 0; k < 16; k++) a += h1[k]*W1[k*16 + c];
            h2[c] = fmaxf((a - B1m[c])*B1s[c] + B1b[c], 0.0f);
        }
        #pragma unroll
        for (int off = 8; off; off >>= 1) {
            #pragma unroll
            for (int c = 0; c < 16; c++)
                h2[c] = fmaxf(h2[c], __shfl_xor_sync(FULLM, h2[c], off));
        }
        if (s == 0) {
            #pragma unroll
            for (int c = 0; c < 16; c++) {
                sr[r*288 + 256 + rI*16 + c] = h2[c];
                feats[(size_t)row*288 + 256 + rI*16 + c] = h2[c];
            }
        }
    }
    __syncthreads();

    // ---- split-k GEMM [8,288]@[288,128] ----
    {
        int half = tid >> 7, outc = tid & 127;
        float acc[8] = {0.f,0.f,0.f,0.f,0.f,0.f,0.f,0.f};
        int kb = half*144;
        for (int k = kb; k < kb + 144; k++) {
            float wv = __ldg(fw + (size_t)k*128 + outc);
            #pragma unroll
            for (int r = 0; r < 8; r++) acc[r] += sr[r*288 + k] * wv;
        }
        #pragma unroll
        for (int r = 0; r < 8; r++) sp[half][r][outc] = acc[r];
    }
    __syncthreads();
    if (tid < 128) {
        int outc = tid;
        float g = fbn[outc], be = fbn[128+outc], m = fbn[256+outc], v = fbn[384+outc];
        float sc = g * (1.0f/sqrtf(v + 1e-5f));
        #pragma unroll
        for (int r = 0; r < 8; r++) {
            float a = sp[0][r][outc] + sp[1][r][outc];
            out[(size_t)(row0 + r)*128 + outc] = fmaxf((a - m)*sc + be, 0.f);
        }
    }
}

// ---------------- launch ----------------
extern "C" void kernel_launch(void* const* d_in, const int* in_sizes, int n_in,
                              void* d_out, int out_size) {
    const float* points = (const float*)d_in[0];
    const float* rng    = (const float*)d_in[1];
    const float* sf     = (const float*)d_in[2];
    const float* sa_w0  = (const float*)d_in[3];
    const float* sa_bn0 = (const float*)d_in[4];
    const float* sa_w1  = (const float*)d_in[5];
    const float* sa_bn1 = (const float*)d_in[6];
    const float* fw     = (const float*)d_in[7];
    const float* fbn    = (const float*)d_in[8];
    float* out = (float*)d_out;

    float* fused  = out;                                          // [4096,128]
    float* feats  = out + (size_t)NROWS*128;                      // [4096,288]
    float* coords = out + (size_t)NROWS*128 + (size_t)NROWS*288;  // [4096,4]

    const int FPS_SMEM = CMPN * (int)sizeof(float4);   // 128 KB
    cudaFuncSetAttribute(fps_kernel, cudaFuncAttributeMaxDynamicSharedMemorySize, FPS_SMEM);

    fps_kernel<<<64, 512, FPS_SMEM>>>(points, rng, coords);
    bevscan_kernel<<<SCANBLK + NROWS/2, 512>>>(sf, feats);
    mlpgemm_kernel<<<NROWS/8, 256>>>(sa_w0, sa_bn0, sa_w1, sa_bn1, fw, fbn, feats, fused);
}